// round 17
// baseline (speedup 1.0000x reference)
#include <cuda_runtime.h>

#define S 64
#define D 524288            // 512*32*32
#define DQ (D / 4)          // 131072 float4 columns per row

// ---- pass 1 tiling: 512 float4 cols per block (2 per thread), 8-row group ----
#define P1_THREADS 256
#define P1_CC (DQ / (2 * P1_THREADS))   // 256 column chunks
#define SGROUPS 8

// ---- pass 3 tiling: 256 float4 cols per block, 8-row group ----
#define P3_THREADS 256
#define P3_CC (DQ / P3_THREADS)         // 512

// scratch (no device allocations allowed)
__device__ float g_part[128 * P1_CC];
__device__ float g_sums[128];               // stage-1 reduced targets
__device__ float g_coeff[3 * S];            // [cp(64)][cc(64)][cn(64)]

__device__ __forceinline__ float dot4(float4 a, float4 b) {
    return a.x * b.x + a.y * b.y + a.z * b.z + a.w * b.w;
}

// 32-byte evict_last load (the only ld width ptxas accepts with this hint on
// sm_103): pins the input lines at high L2 retention priority.
__device__ __forceinline__ void ldg_el8(const float4* p, float4& a, float4& b) {
    unsigned int r0, r1, r2, r3, r4, r5, r6, r7;
    asm("ld.global.nc.L2::evict_last.v8.b32 {%0,%1,%2,%3,%4,%5,%6,%7}, [%8];"
        : "=r"(r0), "=r"(r1), "=r"(r2), "=r"(r3),
          "=r"(r4), "=r"(r5), "=r"(r6), "=r"(r7)
        : "l"(p));
    a.x = __uint_as_float(r0); a.y = __uint_as_float(r1);
    a.z = __uint_as_float(r2); a.w = __uint_as_float(r3);
    b.x = __uint_as_float(r4); b.y = __uint_as_float(r5);
    b.z = __uint_as_float(r6); b.w = __uint_as_float(r7);
}

// Pass 1: block = (col chunk cx, s-group sg). Each thread owns one 32B column
// pair. The 9-row window is processed as two 5-row half-batches with a 1-row
// register carry (peak ~40 live data floats). All input loads are evict_last
// so the whole 128MB input (~L2 capacity) stays resident for pass 3.
__global__ __launch_bounds__(P1_THREADS) void dots_kernel(const float4* __restrict__ q4) {
    const int sg = blockIdx.y;
    const int s0 = sg * 8;
    const int cp8 = blockIdx.x * (2 * P1_THREADS) + 2 * threadIdx.x;  // even float4 idx

    float4 a[5], b[5];
    float v[16];

    // half 1: rows s0 .. s0+4 (front-batched, MLP=5 x 32B)
#pragma unroll
    for (int k = 0; k < 5; k++)
        ldg_el8(&q4[(size_t)(s0 + k) * DQ + cp8], a[k], b[k]);
#pragma unroll
    for (int k = 0; k < 4; k++) {
        v[k]     = dot4(a[k], a[k])     + dot4(b[k], b[k]);         // N[s0+k]
        v[k + 8] = dot4(a[k], a[k + 1]) + dot4(b[k], b[k + 1]);     // A[s0+k]
    }

    // half 2: carry row s0+4, load rows s0+5 .. s0+8
    a[0] = a[4]; b[0] = b[4];
#pragma unroll
    for (int k = 1; k < 5; k++) {
        int row = s0 + 4 + k;
        if (row > S - 1) row = S - 1;   // sg==7 halo; its A[63] is never read
        ldg_el8(&q4[(size_t)row * DQ + cp8], a[k], b[k]);
    }
#pragma unroll
    for (int k = 0; k < 4; k++) {
        v[4 + k]  = dot4(a[k], a[k])     + dot4(b[k], b[k]);        // N[s0+4+k]
        v[12 + k] = dot4(a[k], a[k + 1]) + dot4(b[k], b[k + 1]);    // A[s0+4+k]
    }

    // conflict-free smem transpose reduction (16 STS + 16 LDS + 1 SHFL)
    __shared__ float sh[16][P1_THREADS + 1];
#pragma unroll
    for (int k = 0; k < 16; k++) sh[k][threadIdx.x] = v[k];
    __syncthreads();

    const int kk  = threadIdx.x & 15;
    const int seg = threadIdx.x >> 4;
    float acc = 0.f;
#pragma unroll
    for (int j = 0; j < 16; j++) acc += sh[kk][seg * 16 + j];
    acc += __shfl_xor_sync(0xFFFFFFFFu, acc, 16);

    __shared__ float sh2[16][9];
    const int w = threadIdx.x >> 5;
    if ((threadIdx.x & 16) == 0)
        sh2[kk][w] = acc;
    __syncthreads();

    if (threadIdx.x < 16) {
        float sum = 0.f;
#pragma unroll
        for (int j = 0; j < 8; j++) sum += sh2[threadIdx.x][j];
        g_part[(threadIdx.x * 8 + sg) * P1_CC + blockIdx.x] = sum;
    }
}

// Pass 2a: parallel reduction of the 128 targets (one block each, 1KB coalesced).
__global__ __launch_bounds__(128) void coeff_stage1(void) {
    const float* src = g_part + (size_t)blockIdx.x * P1_CC;
    float acc = 0.f;
#pragma unroll
    for (int m = 0; m < P1_CC / 128; m++)
        acc += src[threadIdx.x + 128 * m];

#pragma unroll
    for (int off = 16; off > 0; off >>= 1)
        acc += __shfl_xor_sync(0xFFFFFFFFu, acc, off);

    __shared__ float sw[4];
    const int w    = threadIdx.x >> 5;
    const int lane = threadIdx.x & 31;
    if (lane == 0) sw[w] = acc;
    __syncthreads();
    if (threadIdx.x == 0)
        g_sums[blockIdx.x] = sw[0] + sw[1] + sw[2] + sw[3];
}

// Pass 2b (tiny): entropy branch ladder + softmax-of-2 -> (cp, cc, cn).
__global__ void coeff_stage2(const float* __restrict__ ent) {
    const int s = threadIdx.x;
    __shared__ float shN[S], shA[S];
    if (s < S) {
        const int pN = (s & 7) * 8 + (s >> 3);
        shN[s] = g_sums[pN];
        shA[s] = g_sums[pN + 64];
    }
    __syncthreads();
    if (s >= S) return;

    int k1, k2;
    if (s == 0) {
        const int b0 = (ent[0] >= ent[1]) ? 1 : 0;
        k1 = b0; k2 = b0;
    } else if (s == S - 1) {
        const int bL = (ent[S - 1] >= ent[S - 2]) ? (S - 2) : (S - 1);
        k1 = bL; k2 = bL;
    } else {
        const float e  = ent[s];
        const float ep = ent[s - 1];
        const float en = ent[s + 1];
        const bool ge_next = e >= en, ge_prev = e >= ep;
        const bool le_next = e <= en, le_prev = e <= ep;
        if (ge_next && ge_prev)      { k1 = s - 1; k2 = s + 1; }
        else if (le_next && ge_prev) { k1 = s - 1; k2 = s;     }
        else if (ge_next && le_prev) { k1 = s;     k2 = s + 1; }
        else                         { k1 = s;     k2 = s;     }
    }

    const float d1 = (k1 == s) ? shN[s] : ((k1 == s - 1) ? shA[s - 1] : shA[s]);
    const float d2 = (k2 == s) ? shN[s] : ((k2 == s - 1) ? shA[s - 1] : shA[s]);

    const float scale = rsqrtf((float)D);
    const float s1 = d1 * scale, s2 = d2 * scale;
    const float m  = fmaxf(s1, s2);
    float w1 = expf(s1 - m), w2 = expf(s2 - m);
    const float inv = 1.f / (w1 + w2);
    w1 *= inv; w2 *= inv;

    float cp = 0.f, cc = 0.f, cn = 0.f;
    if (k1 == s - 1) cp += w1; else if (k1 == s) cc += w1; else cn += w1;
    if (k2 == s - 1) cp += w2; else if (k2 == s) cc += w2; else cn += w2;

    g_coeff[s]       = cp;
    g_coeff[64 + s]  = cc;
    g_coeff[128 + s] = cn;
}

// Pass 3: out[s] = cp[s]*q[s-1] + cc[s]*q[s] + cn[s]*q[s+1].
// Reads should now hit the evict_last-pinned input in L2 (hits don't demote
// the priority). Output uses streaming stores (evict-first) so the 128MB
// write stream can't displace the pinned input.
__global__ __launch_bounds__(P3_THREADS) void out_kernel(const float4* __restrict__ q4,
                                                         float4* __restrict__ o4) {
    const int sg  = blockIdx.y;
    const int s0  = sg * 8;
    const int col = blockIdx.x * P3_THREADS + threadIdx.x;

    __shared__ float scp[8], scc[8], scn[8];
    if (threadIdx.x < 8) {
        scp[threadIdx.x] = g_coeff[s0 + threadIdx.x];
        scc[threadIdx.x] = g_coeff[64 + s0 + threadIdx.x];
        scn[threadIdx.x] = g_coeff[128 + s0 + threadIdx.x];
    }
    __syncthreads();

    // rows s0-1 .. s0+8, clamped; clamped halos are multiplied by zero coeffs
    float4 r[10];
#pragma unroll
    for (int k = 0; k < 10; k++) {
        int row = s0 - 1 + k;
        if (row < 0) row = 0;
        if (row > S - 1) row = S - 1;
        r[k] = __ldg(&q4[(size_t)row * DQ + col]);
    }

#pragma unroll
    for (int i = 0; i < 8; i++) {
        const float cp = scp[i], cc = scc[i], cn = scn[i];
        float4 o;
        o.x = cp * r[i].x + cc * r[i + 1].x + cn * r[i + 2].x;
        o.y = cp * r[i].y + cc * r[i + 1].y + cn * r[i + 2].y;
        o.z = cp * r[i].z + cc * r[i + 1].z + cn * r[i + 2].z;
        o.w = cp * r[i].w + cc * r[i + 1].w + cn * r[i + 2].w;
        __stcs(&o4[(size_t)(s0 + i) * DQ + col], o);
    }
}

extern "C" void kernel_launch(void* const* d_in, const int* in_sizes, int n_in,
                              void* d_out, int out_size) {
    const float4* q4  = (const float4*)d_in[0];
    const float*  ent = (const float*)d_in[1];
    float4*       o4  = (float4*)d_out;

    dots_kernel<<<dim3(P1_CC, SGROUPS), P1_THREADS>>>(q4);
    coeff_stage1<<<128, 128>>>();
    coeff_stage2<<<1, 64>>>(ent);
    out_kernel<<<dim3(P3_CC, SGROUPS), P3_THREADS>>>(q4, o4);
}